// round 16
// baseline (speedup 1.0000x reference)
#include <cuda_runtime.h>
#include <cuda_fp16.h>
#include <cstdint>

#define NN 20000
#define NE 320000

// ---------------- single aligned device scratch (float-unit offsets) ----------
#define OFF_CNT 0
#define SZ_CNT  20480
#define OFF_AGG (OFF_CNT + SZ_CNT)
#define SZ_AGG  (NN * 512)
#define OFF_H1  (OFF_AGG + SZ_AGG)
#define SZ_H1   (NN * 512)
#define OFF_H2  (OFF_H1 + SZ_H1)
#define SZ_H2   (NN * 512)
#define OFF_H3  (OFF_H2 + SZ_H2)
#define SZ_H3   (NN * 1024)
#define OFF_W1L (OFF_H3 + SZ_H3)
#define OFF_W1R (OFF_W1L + 512*256)
#define OFF_W2L (OFF_W1R + 512*256)
#define OFF_W2R (OFF_W2L + 512*512)
#define OFF_W3L (OFF_W2R + 512*512)
#define OFF_W3R (OFF_W3L + 1024*512)
#define OFF_WFC (OFF_W3R + 1024*512)
#define OFF_XC  (OFF_WFC + 512*1024)
#define OFF_RP   (OFF_XC + NN*256)
#define OFF_FILL (OFF_RP + 20512)
#define OFF_CSR  (OFF_FILL + 20480)
#define SZ_TOTAL (OFF_CSR + NE)

__device__ __align__(128) float g_scratch[SZ_TOTAL];   // zero-initialized at load

// software grid barrier state (zero-initialized; gen is monotonic across replays)
__device__ int g_bar_count;
__device__ volatile int g_bar_gen;

__device__ __forceinline__ void grid_barrier(int nblocks) {
    __syncthreads();
    if (threadIdx.x == 0) {
        int gen = g_bar_gen;
        __threadfence();
        int t = atomicAdd(&g_bar_count, 1);
        if (t == nblocks - 1) {
            g_bar_count = 0;
            __threadfence();
            g_bar_gen = gen + 1;
        } else {
            while (g_bar_gen == gen) { }
        }
        __threadfence();
    }
    __syncthreads();
}

__device__ __forceinline__ uint32_t smem_u32(const void* p) {
    uint32_t a;
    asm("{ .reg .u64 t; cvta.to.shared.u64 t, %1; cvt.u32.u64 %0, t; }" : "=r"(a) : "l"(p));
    return a;
}

// ---------------- merged prep: transposes + x->fp16 + degree count --------------
// blocks [0,2304): transall; [2304,2624): cvt x; [2624,2936): count edges
// cnt was zeroed by the previous csr_kernel run (or static zero-init on first run).
__global__ void prep_kernel(const float* __restrict__ W1l, const float* __restrict__ W1r,
                            const float* __restrict__ W2l, const float* __restrict__ W2r,
                            const float* __restrict__ W3l, const float* __restrict__ W3r,
                            const float* __restrict__ Wfc, const float* __restrict__ x,
                            const int* __restrict__ ei, int E) {
    int b = blockIdx.x;
    int tid = threadIdx.y * 32 + threadIdx.x;   // block (32,8) = 256
    if (b >= 2624) {
        int* cnt = (int*)(g_scratch + OFF_CNT);
        int i = (b - 2624) * 256 + tid;
        int stride = 312 * 256;
        for (; i < E; i += stride) atomicAdd(&cnt[ei[E + i]], 1);
        return;
    }
    if (b >= 2304) {
        __half* dst = (__half*)(g_scratch + OFF_XC);
        int i = (b - 2304) * 256 + tid;
        int stride = 320 * 256;
        int n4 = NN * 256 / 4;
        for (; i < n4; i += stride) {
            float4 v = ((const float4*)x)[i];
            half2 h0 = __floats2half2_rn(v.x, v.y);
            half2 h1 = __floats2half2_rn(v.z, v.w);
            uint2 w; w.x = *(uint32_t*)&h0; w.y = *(uint32_t*)&h1;
            *(uint2*)(dst + i * 4) = w;
        }
        return;
    }
    __shared__ float t[32][33];
    const float* src; int dstOff, K, N, lt;
    if      (b < 128)  { src = W1l; dstOff = OFF_W1L; K = 256;  N = 512;  lt = b; }
    else if (b < 256)  { src = W1r; dstOff = OFF_W1R; K = 256;  N = 512;  lt = b - 128; }
    else if (b < 512)  { src = W2l; dstOff = OFF_W2L; K = 512;  N = 512;  lt = b - 256; }
    else if (b < 768)  { src = W2r; dstOff = OFF_W2R; K = 512;  N = 512;  lt = b - 512; }
    else if (b < 1280) { src = W3l; dstOff = OFF_W3L; K = 512;  N = 1024; lt = b - 768; }
    else if (b < 1792) { src = W3r; dstOff = OFF_W3R; K = 512;  N = 1024; lt = b - 1280; }
    else               { src = Wfc; dstOff = OFF_WFC; K = 1024; N = 512;  lt = b - 1792; }
    int ntx = N >> 5;
    int nb = (lt % ntx) * 32, kb = (lt / ntx) * 32;
    int tx = threadIdx.x, ty = threadIdx.y;
    for (int i = ty; i < 32; i += 8)
        t[i][tx] = src[(size_t)(kb + i) * N + nb + tx];
    __syncthreads();
    __half* dst = (__half*)(g_scratch + dstOff);
    for (int i = ty; i < 32; i += 8)
        dst[(size_t)(nb + i) * K + kb + tx] = __float2half_rn(t[tx][i]);
}

// ---------------- fused CSR: prefix -> barrier -> fill -> barrier -> re-zero ----
#define CSR_BLOCKS 148
__global__ void csr_kernel(const int* __restrict__ ei, int E) {
    const int tid = threadIdx.x;
    int* rp = (int*)(g_scratch + OFF_RP);
    int* cnt = (int*)(g_scratch + OFF_CNT);
    int* fill = (int*)(g_scratch + OFF_FILL);
    int* csr = (int*)(g_scratch + OFF_CSR);

    // phase 1: prefix scan (CTA 0 only; 256 threads x chunk 80, double read of cnt)
    if (blockIdx.x == 0) {
        const int CH = 80;                        // 256*80 = 20480 >= NN
        int beg = tid * CH;
        int s = 0;
        for (int j = 0; j < CH; j++) {
            int i = beg + j;
            if (i < NN) s += cnt[i];
        }
        int lane = tid & 31, wid = tid >> 5;
        int sc = s;
#pragma unroll
        for (int o = 1; o < 32; o <<= 1) {
            int t = __shfl_up_sync(~0u, sc, o);
            if (lane >= o) sc += t;
        }
        __shared__ int wsum[8];
        if (lane == 31) wsum[wid] = sc;
        __syncthreads();
        if (wid == 0 && lane < 8) {
            int w = wsum[lane];
#pragma unroll
            for (int o = 1; o < 8; o <<= 1) {
                int t = __shfl_up_sync(0xFFu, w, o);
                if (lane >= o) w += t;
            }
            wsum[lane] = w;
        }
        __syncthreads();
        int run = sc - s + ((wid > 0) ? wsum[wid - 1] : 0);
        if (tid == 0) rp[0] = 0;
        for (int j = 0; j < CH; j++) {
            int i = beg + j;
            if (i < NN) { run += cnt[i]; rp[i + 1] = run; }
        }
    }
    grid_barrier(CSR_BLOCKS);

    // phase 2: fill CSR
    {
        int i = blockIdx.x * blockDim.x + tid;
        int stride = CSR_BLOCKS * blockDim.x;
        for (; i < E; i += stride) {
            int s = ei[i];
            int t = ei[E + i];
            int pos = rp[t] + atomicAdd(&fill[t], 1);
            csr[pos] = s;
        }
    }
    grid_barrier(CSR_BLOCKS);

    // phase 3: re-zero cnt + fill for the next graph replay (int4)
    {
        int i = blockIdx.x * blockDim.x + tid;
        int stride = CSR_BLOCKS * blockDim.x;
        int4 z = make_int4(0, 0, 0, 0);
        for (int j = i; j < SZ_CNT / 4; j += stride) ((int4*)cnt)[j] = z;
        for (int j = i; j < 20480 / 4; j += stride) ((int4*)fill)[j] = z;
    }
}

// ---------------- gather-mean: fp16 in/out, 4-edge unroll -----------------------
__global__ void gather_f16(int xoff, int d) {
    const __half* x = (const __half*)(g_scratch + xoff);
    __half* agg = (__half*)(g_scratch + OFF_AGG);
    const int* rp = (const int*)(g_scratch + OFF_RP);
    const int* csr = (const int*)(g_scratch + OFF_CSR);
    int node = (blockIdx.x * blockDim.x + threadIdx.x) >> 5;
    int lane = threadIdx.x & 31;
    if (node >= NN) return;
    int beg = rp[node], end = rp[node + 1];
    const int nv = d >> 8;

    float2 acc[8];
#pragma unroll
    for (int v = 0; v < 8; v++) acc[v] = make_float2(0.f, 0.f);

    int e = beg;
    for (; e + 3 < end; e += 4) {
        const __half* x0 = x + (size_t)csr[e] * d;
        const __half* x1 = x + (size_t)csr[e + 1] * d;
        const __half* x2 = x + (size_t)csr[e + 2] * d;
        const __half* x3 = x + (size_t)csr[e + 3] * d;
#pragma unroll 2
        for (int v = 0; v < nv; v++) {
            uint4 ra = *(const uint4*)(x0 + lane * 8 + v * 256);
            uint4 rb = *(const uint4*)(x1 + lane * 8 + v * 256);
            uint4 rc = *(const uint4*)(x2 + lane * 8 + v * 256);
            uint4 rd = *(const uint4*)(x3 + lane * 8 + v * 256);
#pragma unroll
            for (int q = 0; q < 4; q++) {
                uint32_t wa = (&ra.x)[q], wb = (&rb.x)[q], wc = (&rc.x)[q], wd = (&rd.x)[q];
                float2 fa = __half22float2(*(half2*)&wa);
                float2 fb = __half22float2(*(half2*)&wb);
                float2 fc = __half22float2(*(half2*)&wc);
                float2 fd = __half22float2(*(half2*)&wd);
                acc[v*4+q].x += (fa.x + fb.x) + (fc.x + fd.x);
                acc[v*4+q].y += (fa.y + fb.y) + (fc.y + fd.y);
            }
        }
    }
    for (; e < end; e++) {
        const __half* x0 = x + (size_t)csr[e] * d;
#pragma unroll 2
        for (int v = 0; v < nv; v++) {
            uint4 ra = *(const uint4*)(x0 + lane * 8 + v * 256);
#pragma unroll
            for (int q = 0; q < 4; q++) {
                uint32_t wa = (&ra.x)[q];
                float2 fa = __half22float2(*(half2*)&wa);
                acc[v*4+q].x += fa.x;
                acc[v*4+q].y += fa.y;
            }
        }
    }
    float sc = 1.0f / (float)max(end - beg, 1);
    __half* out = agg + (size_t)node * d + lane * 8;
#pragma unroll 2
    for (int v = 0; v < nv; v++) {
        uint4 w;
#pragma unroll
        for (int q = 0; q < 4; q++) {
            half2 h = __floats2half2_rn(acc[v*4+q].x * sc, acc[v*4+q].y * sc);
            (&w.x)[q] = *(uint32_t*)&h;
        }
        *(uint4*)(out + v * 256) = w;
    }
}

// ---------------- fp16 mma.sync GEMM, 4-stage cp.async + ldmatrix ---------------
#define BM 128
#define BN 128
#define BKC 32
#define PADH 40
#define NSTG 4
#define STG_H (BM * PADH)
#define SMEM_GEMM (NSTG * STG_H * 2 * 2)

__global__ __launch_bounds__(256, 2)
void gemm_mma(int a1off, int a2off, int hasA2,
              int b1off, int b2off, const float* __restrict__ bias,
              int coff, float* cext, int M, int N, int K, int doRelu, int outHalf) {
    extern __shared__ __half smh[];
    __half* sA = smh;
    __half* sB = smh + NSTG * STG_H;

    const __half* A1 = (const __half*)(g_scratch + a1off);
    const __half* A2 = (const __half*)(g_scratch + a2off);
    const __half* B1 = (const __half*)(g_scratch + b1off);
    const __half* B2 = (const __half*)(g_scratch + b2off);
    float* Cf = (coff >= 0) ? (g_scratch + coff) : cext;
    __half* Ch = (__half*)Cf;

    const int tid = threadIdx.x, wid = tid >> 5, lane = tid & 31;
    const int rowBase = blockIdx.y * BM;
    const int colBase = blockIdx.x * BN;
    const int wm = (wid >> 2) * 64;
    const int wn = (wid & 3) * 32;
    const int lr = tid >> 2;
    const int lc8 = (tid & 3) * 8;
    const int qrow = lane >> 2;
    const int qcol = lane & 3;

    const uint32_t sAu = smem_u32(sA);
    const uint32_t sBu = smem_u32(sB);

    const int aRow = wm + (lane & 15);
    const int aColSel = (lane & 16) ? 8 : 0;
    const int bRow = wn + (lane & 7) + ((lane & 16) ? 8 : 0);
    const int bColSel = (lane & 8) ? 8 : 0;

    float acc[4][4][4];
#pragma unroll
    for (int mi = 0; mi < 4; mi++)
#pragma unroll
        for (int ni = 0; ni < 4; ni++)
#pragma unroll
            for (int r = 0; r < 4; r++) acc[mi][ni][r] = 0.f;

    const int Ktot = hasA2 ? 2 * K : K;
    const int nch = Ktot / BKC;

    auto load_stage = [&](int c) {
        int stg = c & (NSTG - 1);
        int k0 = c * BKC;
        const __half* A; const __half* B; int kk;
        if (k0 < K) { A = A1; B = B1; kk = k0; }
        else        { A = A2; B = B2; kk = k0 - K; }
#pragma unroll
        for (int p = 0; p < 2; p++) {
            int row = lr + p * 64;
            int gm = rowBase + row;
            const __half* src = A + (size_t)gm * K + kk + lc8;
            uint32_t dst = sAu + (uint32_t)(stg * STG_H + row * PADH + lc8) * 2u;
            uint32_t sz = (gm < M) ? 16u : 0u;
            asm volatile("cp.async.cg.shared.global [%0], [%1], 16, %2;"
                         :: "r"(dst), "l"(src), "r"(sz));
        }
#pragma unroll
        for (int p = 0; p < 2; p++) {
            int row = lr + p * 64;
            const __half* src = B + (size_t)(colBase + row) * K + kk + lc8;
            uint32_t dst = sBu + (uint32_t)(stg * STG_H + row * PADH + lc8) * 2u;
            asm volatile("cp.async.cg.shared.global [%0], [%1], 16, %2;"
                         :: "r"(dst), "l"(src), "r"(16u));
        }
    };

#pragma unroll
    for (int i = 0; i < NSTG - 1; i++) {
        if (i < nch) load_stage(i);
        asm volatile("cp.async.commit_group;" ::: "memory");
    }

    for (int ch = 0; ch < nch; ch++) {
        asm volatile("cp.async.wait_group 2;" ::: "memory");
        __syncthreads();

        int pre = ch + NSTG - 1;
        if (pre < nch) load_stage(pre);
        asm volatile("cp.async.commit_group;" ::: "memory");

        const uint32_t stA = sAu + (uint32_t)((ch & (NSTG - 1)) * STG_H) * 2u;
        const uint32_t stB = sBu + (uint32_t)((ch & (NSTG - 1)) * STG_H) * 2u;
#pragma unroll
        for (int ks = 0; ks < 2; ks++) {
            const int kof = ks * 16;
            uint32_t af[4][4], bf[4][2];
#pragma unroll
            for (int mi = 0; mi < 4; mi++) {
                uint32_t addr = stA + (uint32_t)((aRow + mi * 16) * PADH + kof + aColSel) * 2u;
                asm volatile("ldmatrix.sync.aligned.m8n8.x4.shared.b16 {%0,%1,%2,%3}, [%4];"
                             : "=r"(af[mi][0]), "=r"(af[mi][1]),
                               "=r"(af[mi][2]), "=r"(af[mi][3]) : "r"(addr));
            }
#pragma unroll
            for (int j = 0; j < 2; j++) {
                uint32_t addr = stB + (uint32_t)((bRow + j * 16) * PADH + kof + bColSel) * 2u;
                asm volatile("ldmatrix.sync.aligned.m8n8.x4.shared.b16 {%0,%1,%2,%3}, [%4];"
                             : "=r"(bf[2*j][0]), "=r"(bf[2*j][1]),
                               "=r"(bf[2*j+1][0]), "=r"(bf[2*j+1][1]) : "r"(addr));
            }
#pragma unroll
            for (int mi = 0; mi < 4; mi++)
#pragma unroll
                for (int ni = 0; ni < 4; ni++) {
                    asm volatile(
                        "mma.sync.aligned.m16n8k16.row.col.f32.f16.f16.f32 "
                        "{%0,%1,%2,%3}, {%4,%5,%6,%7}, {%8,%9}, {%0,%1,%2,%3};"
                        : "+f"(acc[mi][ni][0]), "+f"(acc[mi][ni][1]),
                          "+f"(acc[mi][ni][2]), "+f"(acc[mi][ni][3])
                        : "r"(af[mi][0]), "r"(af[mi][1]), "r"(af[mi][2]), "r"(af[mi][3]),
                          "r"(bf[ni][0]), "r"(bf[ni][1]));
                }
        }
    }

    // epilogue: hoisted bias loads
    float2 bv[4];
#pragma unroll
    for (int ni = 0; ni < 4; ni++)
        bv[ni] = *(const float2*)(bias + colBase + wn + ni * 8 + 2 * qcol);

#pragma unroll
    for (int mi = 0; mi < 4; mi++) {
        int gm0 = rowBase + wm + mi * 16 + qrow;
        int gm1 = gm0 + 8;
#pragma unroll
        for (int ni = 0; ni < 4; ni++) {
            int col = colBase + wn + ni * 8 + 2 * qcol;
            float r0 = acc[mi][ni][0] + bv[ni].x;
            float r1 = acc[mi][ni][1] + bv[ni].y;
            float r2 = acc[mi][ni][2] + bv[ni].x;
            float r3 = acc[mi][ni][3] + bv[ni].y;
            if (doRelu) {
                r0 = fmaxf(r0, 0.f); r1 = fmaxf(r1, 0.f);
                r2 = fmaxf(r2, 0.f); r3 = fmaxf(r3, 0.f);
            }
            if (outHalf) {
                half2 h0 = __floats2half2_rn(r0, r1);
                half2 h1 = __floats2half2_rn(r2, r3);
                if (gm0 < M) *(half2*)(Ch + (size_t)gm0 * N + col) = h0;
                if (gm1 < M) *(half2*)(Ch + (size_t)gm1 * N + col) = h1;
            } else {
                if (gm0 < M) *(float2*)(Cf + (size_t)gm0 * N + col) = make_float2(r0, r1);
                if (gm1 < M) *(float2*)(Cf + (size_t)gm1 * N + col) = make_float2(r2, r3);
            }
        }
    }
}

// ---------------- launch --------------------------------------------------------
extern "C" void kernel_launch(void* const* d_in, const int* in_sizes, int n_in,
                              void* d_out, int out_size) {
    const float* x   = (const float*)d_in[0];
    const int*   ei  = (const int*)d_in[1];
    const float* Wl1 = (const float*)d_in[2];
    const float* bl1 = (const float*)d_in[3];
    const float* Wr1 = (const float*)d_in[4];
    const float* Wl2 = (const float*)d_in[5];
    const float* bl2 = (const float*)d_in[6];
    const float* Wr2 = (const float*)d_in[7];
    const float* Wl3 = (const float*)d_in[8];
    const float* bl3 = (const float*)d_in[9];
    const float* Wr3 = (const float*)d_in[10];
    const float* Wfc = (const float*)d_in[11];
    const float* bfc = (const float*)d_in[12];
    float* out = (float*)d_out;

    cudaFuncSetAttribute(gemm_mma, cudaFuncAttributeMaxDynamicSharedMemorySize, SMEM_GEMM);

    const int M = NN, E = NE;
    dim3 tb(32, 8);

    // prep: transposes + x->fp16 + degree count (cnt pre-zeroed by prior csr run)
    prep_kernel<<<2936, tb>>>(Wl1, Wr1, Wl2, Wr2, Wl3, Wr3, Wfc, x, ei, E);
    // fused CSR: prefix -> fill -> re-zero (software grid barrier, 148 resident CTAs)
    csr_kernel<<<CSR_BLOCKS, 256>>>(ei, E);

    const int gatherBlocks = (NN * 32 + 255) / 256;
    const int gy = (M + BM - 1) / BM;   // 157

    // ---- layer 1: 256 -> 512
    gather_f16<<<gatherBlocks, 256>>>(OFF_XC, 256);
    gemm_mma<<<dim3(512 / BN, gy), 256, SMEM_GEMM>>>(
        OFF_AGG, OFF_XC, 1, OFF_W1L, OFF_W1R, bl1,
        OFF_H1, nullptr, M, 512, 256, 1, 1);

    // ---- layer 2: 512 -> 512
    gather_f16<<<gatherBlocks, 256>>>(OFF_H1, 512);
    gemm_mma<<<dim3(512 / BN, gy), 256, SMEM_GEMM>>>(
        OFF_AGG, OFF_H1, 1, OFF_W2L, OFF_W2R, bl2,
        OFF_H2, nullptr, M, 512, 512, 1, 1);

    // ---- layer 3: 512 -> 1024
    gather_f16<<<gatherBlocks, 256>>>(OFF_H2, 512);
    gemm_mma<<<dim3(1024 / BN, gy), 256, SMEM_GEMM>>>(
        OFF_AGG, OFF_H2, 1, OFF_W3L, OFF_W3R, bl3,
        OFF_H3, nullptr, M, 1024, 512, 1, 1);

    // ---- final FC: 1024 -> 512 (fp32 out)
    gemm_mma<<<dim3(512 / BN, gy), 256, SMEM_GEMM>>>(
        OFF_H3, OFF_H3, 0, OFF_WFC, OFF_WFC, bfc,
        -1, out, M, 512, 1024, 0, 0);
}

// round 17
// speedup vs baseline: 1.1218x; 1.1218x over previous
#include <cuda_runtime.h>
#include <cuda_fp16.h>
#include <cstdint>

#define NN 20000
#define NE 320000

// ---------------- single aligned device scratch (float-unit offsets) ----------
#define OFF_CNT 0
#define SZ_CNT  20480
#define OFF_AGG (OFF_CNT + SZ_CNT)
#define SZ_AGG  (NN * 512)
#define OFF_H1  (OFF_AGG + SZ_AGG)
#define SZ_H1   (NN * 512)
#define OFF_H2  (OFF_H1 + SZ_H1)
#define SZ_H2   (NN * 512)
#define OFF_H3  (OFF_H2 + SZ_H2)
#define SZ_H3   (NN * 1024)
#define OFF_W1L (OFF_H3 + SZ_H3)
#define OFF_W1R (OFF_W1L + 512*256)
#define OFF_W2L (OFF_W1R + 512*256)
#define OFF_W2R (OFF_W2L + 512*512)
#define OFF_W3L (OFF_W2R + 512*512)
#define OFF_W3R (OFF_W3L + 1024*512)
#define OFF_WFC (OFF_W3R + 1024*512)
#define OFF_XC  (OFF_WFC + 512*1024)
#define OFF_RP   (OFF_XC + NN*256)
#define OFF_FILL (OFF_RP + 20512)
#define OFF_CSR  (OFF_FILL + 20480)
#define SZ_TOTAL (OFF_CSR + NE)

__device__ __align__(128) float g_scratch[SZ_TOTAL];

__device__ __forceinline__ uint32_t smem_u32(const void* p) {
    uint32_t a;
    asm("{ .reg .u64 t; cvta.to.shared.u64 t, %1; cvt.u32.u64 %0, t; }" : "=r"(a) : "l"(p));
    return a;
}

__device__ __forceinline__ void mbar_wait(uint32_t mbar, uint32_t parity) {
    uint32_t done;
    asm volatile(
        "{\n\t.reg .pred p;\n\t"
        "mbarrier.try_wait.parity.acquire.cta.shared::cta.b64 p, [%1], %2;\n\t"
        "selp.b32 %0, 1, 0, p;\n\t}"
        : "=r"(done) : "r"(mbar), "r"(parity) : "memory");
    if (!done) {
        asm volatile(
            "{\n\t.reg .pred P1;\n\t"
            "WAIT_LOOP_%=:\n\t"
            "mbarrier.try_wait.parity.acquire.cta.shared::cta.b64 P1, [%0], %1, 0x989680;\n\t"
            "@P1 bra.uni WAIT_DONE_%=;\n\t"
            "bra.uni WAIT_LOOP_%=;\n\t"
            "WAIT_DONE_%=:\n\t}"
            :: "r"(mbar), "r"(parity) : "memory");
    }
}

// tiled-swizzled weight layout: per matrix [N/128 tiles][K/32 chunks][128 rows][64B]
// byte within 64B row: b' = b ^ (((r>>1)&3)<<4)  (conflict-free for ldmatrix)
__device__ __forceinline__ size_t wtile_idx(int n, int k, int K) {
    int t = n >> 7, r = n & 127, c = k >> 5;
    int b = (k & 31) * 2;
    b ^= ((r >> 1) & 3) << 4;
    return ((size_t)(t * (K >> 5) + c) * 128 + r) * 32 + (b >> 1);
}

// ---------------- merged prep: transposes(tiled) + x->fp16 + zero ---------------
// blocks [0,2304): transall; [2304,2624): cvt x; [2624,2664): zero cnt+fill
__global__ void prep_kernel(const float* __restrict__ W1l, const float* __restrict__ W1r,
                            const float* __restrict__ W2l, const float* __restrict__ W2r,
                            const float* __restrict__ W3l, const float* __restrict__ W3r,
                            const float* __restrict__ Wfc, const float* __restrict__ x) {
    int b = blockIdx.x;
    int tid = threadIdx.y * 32 + threadIdx.x;
    if (b >= 2624) {
        int i = (b - 2624) * 256 + tid;
        int4 z = make_int4(0, 0, 0, 0);
        if (i < SZ_CNT / 4) ((int4*)(g_scratch + OFF_CNT))[i] = z;
        if (i < 20480 / 4) ((int4*)(g_scratch + OFF_FILL))[i] = z;
        return;
    }
    if (b >= 2304) {
        __half* dst = (__half*)(g_scratch + OFF_XC);
        int i = (b - 2304) * 256 + tid;
        int stride = 320 * 256;
        int n4 = NN * 256 / 4;
        for (; i < n4; i += stride) {
            float4 v = ((const float4*)x)[i];
            half2 h0 = __floats2half2_rn(v.x, v.y);
            half2 h1 = __floats2half2_rn(v.z, v.w);
            uint2 w; w.x = *(uint32_t*)&h0; w.y = *(uint32_t*)&h1;
            *(uint2*)(dst + i * 4) = w;
        }
        return;
    }
    __shared__ float t[32][33];
    const float* src; int dstOff, K, N, lt;
    if      (b < 128)  { src = W1l; dstOff = OFF_W1L; K = 256;  N = 512;  lt = b; }
    else if (b < 256)  { src = W1r; dstOff = OFF_W1R; K = 256;  N = 512;  lt = b - 128; }
    else if (b < 512)  { src = W2l; dstOff = OFF_W2L; K = 512;  N = 512;  lt = b - 256; }
    else if (b < 768)  { src = W2r; dstOff = OFF_W2R; K = 512;  N = 512;  lt = b - 512; }
    else if (b < 1280) { src = W3l; dstOff = OFF_W3L; K = 512;  N = 1024; lt = b - 768; }
    else if (b < 1792) { src = W3r; dstOff = OFF_W3R; K = 512;  N = 1024; lt = b - 1280; }
    else               { src = Wfc; dstOff = OFF_WFC; K = 1024; N = 512;  lt = b - 1792; }
    int ntx = N >> 5;
    int nb = (lt % ntx) * 32, kb = (lt / ntx) * 32;
    int tx = threadIdx.x, ty = threadIdx.y;
    for (int i = ty; i < 32; i += 8)
        t[i][tx] = src[(size_t)(kb + i) * N + nb + tx];
    __syncthreads();
    __half* dst = (__half*)(g_scratch + dstOff);
    for (int i = ty; i < 32; i += 8) {
        int n = nb + i, k = kb + tx;
        dst[wtile_idx(n, k, K)] = __float2half_rn(t[tx][i]);
    }
}

// ---------------- degree count (int) -------------------------------------------
__global__ void count_kernel(const int* __restrict__ ei, int E) {
    int* cnt = (int*)(g_scratch + OFF_CNT);
    int i = blockIdx.x * blockDim.x + threadIdx.x;
    int stride = gridDim.x * blockDim.x;
    for (; i < E; i += stride) atomicAdd(&cnt[ei[E + i]], 1);
}

// ---------------- prefix sum (chunked, warp-shfl block scan) --------------------
#define PCH 20
__global__ void prefix_kernel() {
    const int tid = threadIdx.x;
    int* rp = (int*)(g_scratch + OFF_RP);
    const int* cnt = (const int*)(g_scratch + OFF_CNT);
    int beg = tid * PCH;
    int local[PCH];
    int s = 0;
#pragma unroll
    for (int j = 0; j < PCH; j++) {
        int i = beg + j;
        int v = (i < NN) ? cnt[i] : 0;
        local[j] = v; s += v;
    }
    int lane = tid & 31, wid = tid >> 5;
    int sc = s;
#pragma unroll
    for (int o = 1; o < 32; o <<= 1) {
        int t = __shfl_up_sync(~0u, sc, o);
        if (lane >= o) sc += t;
    }
    __shared__ int wsum[32];
    if (lane == 31) wsum[wid] = sc;
    __syncthreads();
    if (wid == 0) {
        int w = wsum[lane];
#pragma unroll
        for (int o = 1; o < 32; o <<= 1) {
            int t = __shfl_up_sync(~0u, w, o);
            if (lane >= o) w += t;
        }
        wsum[lane] = w;
    }
    __syncthreads();
    int run = sc - s + ((wid > 0) ? wsum[wid - 1] : 0);
    if (tid == 0) rp[0] = 0;
#pragma unroll
    for (int j = 0; j < PCH; j++) {
        int i = beg + j;
        if (i < NN) { run += local[j]; rp[i + 1] = run; }
    }
}

// ---------------- fill CSR ------------------------------------------------------
__global__ void fillcsr_kernel(const int* __restrict__ ei, int E) {
    const int* rp = (const int*)(g_scratch + OFF_RP);
    int* fill = (int*)(g_scratch + OFF_FILL);
    int* csr = (int*)(g_scratch + OFF_CSR);
    int i = blockIdx.x * blockDim.x + threadIdx.x;
    int stride = gridDim.x * blockDim.x;
    for (; i < E; i += stride) {
        int s = ei[i];
        int t = ei[E + i];
        int pos = rp[t] + atomicAdd(&fill[t], 1);
        csr[pos] = s;
    }
}

// ---------------- gather-mean: fp16 in/out, 4-edge unroll -----------------------
__global__ void gather_f16(int xoff, int d) {
    const __half* x = (const __half*)(g_scratch + xoff);
    __half* agg = (__half*)(g_scratch + OFF_AGG);
    const int* rp = (const int*)(g_scratch + OFF_RP);
    const int* csr = (const int*)(g_scratch + OFF_CSR);
    int node = (blockIdx.x * blockDim.x + threadIdx.x) >> 5;
    int lane = threadIdx.x & 31;
    if (node >= NN) return;
    int beg = rp[node], end = rp[node + 1];
    const int nv = d >> 8;

    float2 acc[8];
#pragma unroll
    for (int v = 0; v < 8; v++) acc[v] = make_float2(0.f, 0.f);

    int e = beg;
    for (; e + 3 < end; e += 4) {
        const __half* x0 = x + (size_t)csr[e] * d;
        const __half* x1 = x + (size_t)csr[e + 1] * d;
        const __half* x2 = x + (size_t)csr[e + 2] * d;
        const __half* x3 = x + (size_t)csr[e + 3] * d;
#pragma unroll 2
        for (int v = 0; v < nv; v++) {
            uint4 ra = *(const uint4*)(x0 + lane * 8 + v * 256);
            uint4 rb = *(const uint4*)(x1 + lane * 8 + v * 256);
            uint4 rc = *(const uint4*)(x2 + lane * 8 + v * 256);
            uint4 rd = *(const uint4*)(x3 + lane * 8 + v * 256);
#pragma unroll
            for (int q = 0; q < 4; q++) {
                uint32_t wa = (&ra.x)[q], wb = (&rb.x)[q], wc = (&rc.x)[q], wd = (&rd.x)[q];
                float2 fa = __half22float2(*(half2*)&wa);
                float2 fb = __half22float2(*(half2*)&wb);
                float2 fc = __half22float2(*(half2*)&wc);
                float2 fd = __half22float2(*(half2*)&wd);
                acc[v*4+q].x += (fa.x + fb.x) + (fc.x + fd.x);
                acc[v*4+q].y += (fa.y + fb.y) + (fc.y + fd.y);
            }
        }
    }
    for (; e < end; e++) {
        const __half* x0 = x + (size_t)csr[e] * d;
#pragma unroll 2
        for (int v = 0; v < nv; v++) {
            uint4 ra = *(const uint4*)(x0 + lane * 8 + v * 256);
#pragma unroll
            for (int q = 0; q < 4; q++) {
                uint32_t wa = (&ra.x)[q];
                float2 fa = __half22float2(*(half2*)&wa);
                acc[v*4+q].x += fa.x;
                acc[v*4+q].y += fa.y;
            }
        }
    }
    float sc = 1.0f / (float)max(end - beg, 1);
    __half* out = agg + (size_t)node * d + lane * 8;
#pragma unroll 2
    for (int v = 0; v < nv; v++) {
        uint4 w;
#pragma unroll
        for (int q = 0; q < 4; q++) {
            half2 h = __floats2half2_rn(acc[v*4+q].x * sc, acc[v*4+q].y * sc);
            (&w.x)[q] = *(uint32_t*)&h;
        }
        *(uint4*)(out + v * 256) = w;
    }
}

// ---------------- fp16 mma.sync GEMM: A via cp.async, B via cp.async.bulk -------
#define BM 128
#define BN 128
#define BKC 32
#define PADH 40
#define NSTG 4
#define STG_H (BM * PADH)                  /* A stage: halves */
#define SM_A_BYTES (NSTG * STG_H * 2)      /* 40960 */
#define B_STG_BYTES 8192                   /* B stage: 128 rows x 64B, tiled+swizzled */
#define SMEM_GEMM (SM_A_BYTES + NSTG * B_STG_BYTES)   /* 73728 */

__global__ __launch_bounds__(256, 2)
void gemm_mma(int a1off, int a2off, int hasA2,
              int b1off, int b2off, const float* __restrict__ bias,
              int coff, float* cext, int M, int N, int K, int doRelu, int outHalf) {
    extern __shared__ __half smh[];
    __shared__ __align__(8) uint64_t mbars[NSTG];

    const __half* A1 = (const __half*)(g_scratch + a1off);
    const __half* A2 = (const __half*)(g_scratch + a2off);
    const __half* B1 = (const __half*)(g_scratch + b1off);
    const __half* B2 = (const __half*)(g_scratch + b2off);
    float* Cf = (coff >= 0) ? (g_scratch + coff) : cext;
    __half* Ch = (__half*)Cf;

    const int tid = threadIdx.x, wid = tid >> 5, lane = tid & 31;
    const int rowBase = blockIdx.y * BM;
    const int colBase = blockIdx.x * BN;
    const int wm = (wid >> 2) * 64;
    const int wn = (wid & 3) * 32;
    const int lr = tid >> 2;
    const int lc8 = (tid & 3) * 8;
    const int qrow = lane >> 2;
    const int qcol = lane & 3;

    const uint32_t sAu = smem_u32(smh);
    const uint32_t sBu = sAu + SM_A_BYTES;
    const uint32_t mb0 = smem_u32(mbars);

    const int aRow = wm + (lane & 15);
    const int aColSel = (lane & 16) ? 8 : 0;
    const int bRow = wn + (lane & 7) + ((lane & 16) ? 8 : 0);
    const int bColSel = (lane & 8) ? 8 : 0;

    const int nch2 = K >> 5;                   // chunks per matrix
    const int Ktot = hasA2 ? 2 * K : K;
    const int nch = Ktot / BKC;

    if (tid == 0) {
#pragma unroll
        for (int s = 0; s < NSTG; s++)
            asm volatile("mbarrier.init.shared.b64 [%0], 1;"
                         :: "r"(mb0 + s * 8) : "memory");
    }
    __syncthreads();

    float acc[4][4][4];
#pragma unroll
    for (int mi = 0; mi < 4; mi++)
#pragma unroll
        for (int ni = 0; ni < 4; ni++)
#pragma unroll
            for (int r = 0; r < 4; r++) acc[mi][ni][r] = 0.f;

    // A stage loader (per-thread cp.async, padded layout)
    auto load_A = [&](int c) {
        int stg = c & (NSTG - 1);
        int k0 = c * BKC;
        const __half* A; int kk;
        if (k0 < K) { A = A1; kk = k0; }
        else        { A = A2; kk = k0 - K; }
#pragma unroll
        for (int p = 0; p < 2; p++) {
            int row = lr + p * 64;
            int gm = rowBase + row;
            const __half* src = A + (size_t)gm * K + kk + lc8;
            uint32_t dst = sAu + (uint32_t)(stg * STG_H + row * PADH + lc8) * 2u;
            uint32_t sz = (gm < M) ? 16u : 0u;
            asm volatile("cp.async.cg.shared.global [%0], [%1], 16, %2;"
                         :: "r"(dst), "l"(src), "r"(sz));
        }
    };
    // B stage loader: one bulk copy (tid 0)
    auto load_B = [&](int c) {
        int stg = c & (NSTG - 1);
        int k0 = c * BKC;
        const __half* B; int cl;
        if (k0 < K) { B = B1; cl = k0 >> 5; }
        else        { B = B2; cl = (k0 - K) >> 5; }
        const __half* src = B + ((size_t)(blockIdx.x * nch2 + cl) << 12);
        uint32_t dst = sBu + stg * B_STG_BYTES;
        uint32_t mbar = mb0 + stg * 8;
        asm volatile("mbarrier.arrive.expect_tx.shared.b64 _, [%0], %1;"
                     :: "r"(mbar), "r"((uint32_t)B_STG_BYTES) : "memory");
        asm volatile("cp.async.bulk.shared::cluster.global.mbarrier::complete_tx::bytes "
                     "[%0], [%1], %2, [%3];"
                     :: "r"(dst), "l"(src), "r"((uint32_t)B_STG_BYTES), "r"(mbar) : "memory");
    };

    // prologue
#pragma unroll
    for (int i = 0; i < NSTG - 1; i++) {
        if (i < nch) {
            load_A(i);
            if (tid == 0) load_B(i);
        }
        asm volatile("cp.async.commit_group;" ::: "memory");
    }

    for (int ch = 0; ch < nch; ch++) {
        asm volatile("cp.async.wait_group 2;" ::: "memory");
        mbar_wait(mb0 + (ch & (NSTG - 1)) * 8, (uint32_t)((ch >> 2) & 1));
        __syncthreads();

        int pre = ch + NSTG - 1;
        if (pre < nch) {
            load_A(pre);
            if (tid == 0) load_B(pre);
        }
        asm volatile("cp.async.commit_group;" ::: "memory");

        const uint32_t stA = sAu + (uint32_t)((ch & (NSTG - 1)) * STG_H) * 2u;
        const uint32_t stB = sBu + (uint32_t)((ch & (NSTG - 1)) * B_STG_BYTES);
#pragma unroll
        for (int ks = 0; ks < 2; ks++) {
            const int kof = ks * 16;
            uint32_t af[4][4], bf[4][2];
#pragma unroll
            for (int mi = 0; mi < 4; mi++) {
                uint32_t addr = stA + (uint32_t)((aRow + mi * 16) * PADH + kof + aColSel) * 2u;
                asm volatile("ldmatrix.sync.aligned.m8n8.x4.shared.b16 {%0,%1,%2,%3}, [%4];"
                             : "=r"(af[mi][0]), "=r"(af[mi][1]),
                               "=r"(af[mi][2]), "=r"(af[mi][3]) : "r"(addr));
            }
#pragma unroll
            for (int j = 0; j < 2; j++) {
                int row = bRow + j * 16;
                uint32_t byteoff = (uint32_t)((kof + bColSel) * 2) ^ (uint32_t)(((row >> 1) & 3) << 4);
                uint32_t addr = stB + (uint32_t)row * 64u + byteoff;
                asm volatile("ldmatrix.sync.aligned.m8n8.x4.shared.b16 {%0,%1,%2,%3}, [%4];"
                             : "=r"(bf[2*j][0]), "=r"(bf[2*j][1]),
                               "=r"(bf[2*j+1][0]), "=r"(bf[2*j+1][1]) : "r"(addr));
            }
#pragma unroll
            for (int mi = 0; mi < 4; mi++)
#pragma unroll
                for (int ni = 0; ni < 4; ni++) {
                    asm volatile(
                        "mma.sync.aligned.m16n8k16.row.col.f32.f16.f16.f32 "
                        "{%0,%1,%2,%3}, {%4,%5,%6,%7}, {%8,%9}, {%0,%1,%2,%3};"
                        : "+f"(acc[mi][ni][0]), "+f"(acc[mi][ni][1]),
                          "+f"(acc[mi][ni][2]), "+f"(acc[mi][ni][3])
                        : "r"(af[mi][0]), "r"(af[mi][1]), "r"(af[mi][2]), "r"(af[mi][3]),
                          "r"(bf[ni][0]), "r"(bf[ni][1]));
                }
        }
    }

    // epilogue (hoisted bias)
    float2 bv[4];
#pragma unroll
    for (int ni = 0; ni < 4; ni++)
        bv[ni] = *(const float2*)(bias + colBase + wn + ni * 8 + 2 * qcol);

#pragma unroll
    for (int mi = 0; mi < 4; mi++) {
        int gm0 = rowBase + wm + mi * 16 + qrow;
        int gm1 = gm0 + 8;
#pragma unroll
        for (int ni = 0; ni < 4; ni++) {
            int col = colBase + wn + ni * 8 + 2 * qcol;
            float r0 = acc[mi][ni][0] + bv[ni].x;
            float r1 = acc[mi][ni][1] + bv[ni].y;
            float r2 = acc[mi][ni][2] + bv[ni].x;
            float r3 = acc[mi][ni][3] + bv[ni].y;
            if (doRelu) {
                r0 = fmaxf(r0, 0.f); r1 = fmaxf(r1, 0.f);
                r2 = fmaxf(r2, 0.f); r3 = fmaxf(r3, 0.f);
            }
            if (outHalf) {
                half2 h0 = __floats2half2_rn(r0, r1);
                half2 h1 = __floats2half2_rn(r2, r3);
                if (gm0 < M) *(half2*)(Ch + (size_t)gm0 * N + col) = h0;
                if (gm1 < M) *(half2*)(Ch + (size_t)gm1 * N + col) = h1;
            } else {
                if (gm0 < M) *(float2*)(Cf + (size_t)gm0 * N + col) = make_float2(r0, r1);
                if (gm1 < M) *(float2*)(Cf + (size_t)gm1 * N + col) = make_float2(r2, r3);
            }
        }
    }
}

// ---------------- launch --------------------------------------------------------
extern "C" void kernel_launch(void* const* d_in, const int* in_sizes, int n_in,
                              void* d_out, int out_size) {
    const float* x   = (const float*)d_in[0];
    const int*   ei  = (const int*)d_in[1];
    const float* Wl1 = (const float*)d_in[2];
    const float* bl1 = (const float*)d_in[3];
    const float* Wr1 = (const float*)d_in[4];
    const float* Wl2 = (const float*)d_in[5];
    const float* bl2 = (const float*)d_in[6];
    const float* Wr2 = (const float*)d_in[7];
    const float* Wl3 = (const float*)d_in[8];
    const float* bl3 = (const float*)d_in[9];
    const float* Wr3 = (const float*)d_in[10];
    const float* Wfc = (const float*)d_in[11];
    const float* bfc = (const float*)d_in[12];
    float* out = (float*)d_out;

    cudaFuncSetAttribute(gemm_mma, cudaFuncAttributeMaxDynamicSharedMemorySize, SMEM_GEMM);

    const int M = NN, E = NE;
    dim3 tb(32, 8);

    prep_kernel<<<2664, tb>>>(Wl1, Wr1, Wl2, Wr2, Wl3, Wr3, Wfc, x);
    count_kernel<<<1250, 256>>>(ei, E);
    prefix_kernel<<<1, 1024>>>();
    fillcsr_kernel<<<1250, 256>>>(ei, E);

    const int gatherBlocks = (NN * 32 + 255) / 256;
    const int gy = (M + BM - 1) / BM;   // 157

    // ---- layer 1: 256 -> 512
    gather_f16<<<gatherBlocks, 256>>>(OFF_XC, 256);
    gemm_mma<<<dim3(512 / BN, gy), 256, SMEM_GEMM>>>(
        OFF_AGG, OFF_XC, 1, OFF_W1L, OFF_W1R, bl1,
        OFF_H1, nullptr, M, 512, 256, 1, 1);

    // ---- layer 2: 512 -> 512
    gather_f16<<<gatherBlocks, 256>>>(OFF_H1, 512);
    gemm_mma<<<dim3(512 / BN, gy), 256, SMEM_GEMM>>>(
        OFF_AGG, OFF_H1, 1, OFF_W2L, OFF_W2R, bl2,
        OFF_H2, nullptr, M, 512, 512, 1, 1);

    // ---- layer 3: 512 -> 1024
    gather_f16<<<gatherBlocks, 256>>>(OFF_H2, 512);
    gemm_mma<<<dim3(1024 / BN, gy), 256, SMEM_GEMM>>>(
        OFF_AGG, OFF_H2, 1, OFF_W3L, OFF_W3R, bl3,
        OFF_H3, nullptr, M, 1024, 512, 1, 1);

    // ---- final FC: 1024 -> 512 (fp32 out)
    gemm_mma<<<dim3(512 / BN, gy), 256, SMEM_GEMM>>>(
        OFF_H3, OFF_H3, 0, OFF_WFC, OFF_WFC, bfc,
        -1, out, M, 512, 1024, 0, 0);
}